// round 11
// baseline (speedup 1.0000x reference)
#include <cuda_runtime.h>
#include <cstdint>
#include <mma.h>
using namespace nvcuda;

#define NS 512
#define NR 384
#define CM 256
#define MT (NR*32)       // 12288
#define RT (NR*NR)       // 147456

__device__ float g_L[(size_t)NS * MT];
__device__ float g_R[(size_t)NS * MT];
__device__ float g_rinv[RT];

__device__ __forceinline__ void cp16(uint32_t dst, const float* src) {
    asm volatile("cp.async.cg.shared.global [%0], [%1], 16;\n" :: "r"(dst), "l"(src));
}
__device__ __forceinline__ void cp_commit() {
    asm volatile("cp.async.commit_group;\n" ::);
}
__device__ __forceinline__ void cp_wait1() {
    asm volatile("cp.async.wait_group 1;\n" ::);
}

// ---------------- Kernel 1: LN + left/right projection (fp32 exact) --------
__global__ __launch_bounds__(256) void ln_proj_kernel(
    const float* __restrict__ act, const float* __restrict__ mask,
    const float* __restrict__ gamma, const float* __restrict__ beta,
    const float* __restrict__ lw, const float* __restrict__ lb,
    const float* __restrict__ rw, const float* __restrict__ rb)
{
    extern __shared__ float sm[];
    float* xs    = sm;                 // [64][260]
    float* sW    = sm + 64 * 260;      // [256][64]
    float* smask = sW + 256 * 64;      // [64]
    const int tid  = threadIdx.x;
    const int warp = tid >> 5, lane = tid & 31;
    const int rbase = blockIdx.x * 64;

    for (int i = 0; i < 64; i++) {
        int idx = tid + i * 256;
        int k = idx >> 6, cc = idx & 63;
        sW[idx] = (cc < 32) ? lw[k * 32 + cc] : rw[k * 32 + (cc - 32)];
    }
    for (int rr = 0; rr < 8; rr++) {
        int lr = warp * 8 + rr;
        int r  = rbase + lr;
        const float* arow = act + (size_t)r * CM;
        float x[8], s = 0.f, s2 = 0.f;
        #pragma unroll
        for (int j = 0; j < 8; j++) { x[j] = arow[lane + 32 * j]; s += x[j]; s2 += x[j] * x[j]; }
        #pragma unroll
        for (int o = 16; o > 0; o >>= 1) {
            s  += __shfl_xor_sync(0xffffffffu, s,  o);
            s2 += __shfl_xor_sync(0xffffffffu, s2, o);
        }
        float mu = s * (1.f / 256.f);
        float rstd = rsqrtf(s2 * (1.f / 256.f) - mu * mu + 1e-5f);
        float m = mask[r];
        if (lane == 0) smask[lr] = m;
        #pragma unroll
        for (int j = 0; j < 8; j++) {
            int k = lane + 32 * j;
            xs[lr * 260 + k] = ((x[j] - mu) * rstd * gamma[k] + beta[k]) * m;
        }
    }
    __syncthreads();

    const int tr4 = (tid >> 4) * 4, tc4 = (tid & 15) * 4;
    float acc[4][4] = {};
    for (int k = 0; k < 256; k += 4) {
        float4 w0 = *(const float4*)(sW + (k + 0) * 64 + tc4);
        float4 w1 = *(const float4*)(sW + (k + 1) * 64 + tc4);
        float4 w2 = *(const float4*)(sW + (k + 2) * 64 + tc4);
        float4 w3 = *(const float4*)(sW + (k + 3) * 64 + tc4);
        #pragma unroll
        for (int i = 0; i < 4; i++) {
            float4 xv = *(const float4*)(xs + (tr4 + i) * 260 + k);
            acc[i][0] += xv.x * w0.x + xv.y * w1.x + xv.z * w2.x + xv.w * w3.x;
            acc[i][1] += xv.x * w0.y + xv.y * w1.y + xv.z * w2.y + xv.w * w3.y;
            acc[i][2] += xv.x * w0.z + xv.y * w1.z + xv.z * w2.z + xv.w * w3.z;
            acc[i][3] += xv.x * w0.w + xv.y * w1.w + xv.z * w2.w + xv.w * w3.w;
        }
    }
    float b0, b1, b2, b3;
    if (tc4 < 32) { b0 = lb[tc4]; b1 = lb[tc4+1]; b2 = lb[tc4+2]; b3 = lb[tc4+3]; }
    else { b0 = rb[tc4-32]; b1 = rb[tc4-31]; b2 = rb[tc4-30]; b3 = rb[tc4-29]; }
    #pragma unroll
    for (int i = 0; i < 4; i++) {
        int r = rbase + tr4 + i;
        int aa = r / NR, bb = r % NR;
        float m = smask[tr4 + i];
        float4 o = { acc[i][0] + m * b0, acc[i][1] + m * b1,
                     acc[i][2] + m * b2, acc[i][3] + m * b3 };
        if (tc4 < 32) *(float4*)(g_L + (size_t)aa * MT + bb * 32 + tc4) = o;
        else          *(float4*)(g_R + (size_t)aa * MT + bb * 32 + (tc4 - 32)) = o;
    }
}

// ---------------- Kernel 2: rinv = 1/(eps + mask^T mask) -------------------
__global__ __launch_bounds__(NR) void norm_kernel(const float* __restrict__ mask)
{
    int b = blockIdx.x, d = threadIdx.x;
    float s = 0.f;
    for (int a = 0; a < NS; a++) s += mask[a * NR + b] * mask[a * NR + d];
    g_rinv[b * NR + d] = 1.f / (1e-3f + s);
}

// ---- pipelined stage loaders --------------------------------------------
__device__ __forceinline__ void load_stage_LR(uint32_t smb, int tid, int ks, int s,
                                              int m0, int n0)
{
    uint32_t aA = smb + (uint32_t)s * 12544u * 4u;
    uint32_t aB = aA + 32u * 132u * 4u;
    int k0 = ks * 32;
    #pragma unroll
    for (int i = 0; i < 4; i++) {
        int idx = tid + i * 256;                    // 1024 float4s
        int kk = idx >> 5, c4 = (idx & 31) << 2;
        cp16(aA + (uint32_t)(kk * 132 + c4) * 4u,
             g_L + (size_t)(k0 + kk) * MT + m0 + c4);
    }
    #pragma unroll
    for (int i = 0; i < 8; i++) {
        int idx = tid + i * 256;                    // 2048 float4s
        int kk = idx >> 6, c4 = (idx & 63) << 2;
        cp16(aB + (uint32_t)(kk * 260 + c4) * 4u,
             g_R + (size_t)(k0 + kk) * MT + n0 + c4);
    }
}

__device__ __forceinline__ void load_stage_W(uint32_t smb, int tid, int kc, int s,
                                             const float* __restrict__ ow)
{
    uint32_t aW = smb + (33024u + (uint32_t)s * 4224u) * 4u;
    int k0 = kc * 32;
    #pragma unroll
    for (int i = 0; i < 4; i++) {
        int idx = tid + i * 256;                    // 1024 float4s
        int kk = idx >> 5, f4 = (idx & 31) << 2;
        cp16(aW + (uint32_t)(kk * 132 + f4) * 4u,
             ow + (size_t)(k0 + kk) * 128 + f4);
    }
}

// ---------------- Kernel 3: FUSED  inter = L^T R ;  out = rinv*(inter@W)+ob
// Block tile: 128 m (4 b x 32 c) x 256 n (8 d x 32 e), K=512.
// Each block owns 32 complete rows of inter -> contracts with W in-block.
// smem (floats): phase1: stage s at [s*12544): sA[32][132] + sB[32][260]
//                phase2: sI[32][1032] at 0 ; sW stages at 33024 + s*4224
__global__ __launch_bounds__(256) void gemm_fused_kernel(
    const float* __restrict__ ow, const float* __restrict__ ob,
    float* __restrict__ out)
{
    extern __shared__ float sm[];
    const int tid  = threadIdx.x;
    const int warp = tid >> 5;
    const int wm = warp >> 2, wn = warp & 3;     // 2x4 warp grid of 64x64 slabs
    const int m0 = blockIdx.y * 128, n0 = blockIdx.x * 256;
    const uint32_t smb = (uint32_t)__cvta_generic_to_shared(sm);

    wmma::fragment<wmma::accumulator, 16, 16, 8, float> c[4][4];
    #pragma unroll
    for (int i = 0; i < 4; i++)
        #pragma unroll
        for (int j = 0; j < 4; j++) wmma::fill_fragment(c[i][j], 0.0f);

    // ---- mainloop: double-buffered cp.async, 16 k-chunks of 32 ----
    load_stage_LR(smb, tid, 0, 0, m0, n0);
    cp_commit();
    for (int ks = 0; ks < 16; ks++) {
        int s = ks & 1;
        if (ks + 1 < 16) load_stage_LR(smb, tid, ks + 1, s ^ 1, m0, n0);
        cp_commit();
        cp_wait1();
        __syncthreads();
        float* sA = sm + s * 12544;
        float* sB = sA + 4224;
        #pragma unroll
        for (int kk = 0; kk < 32; kk += 8) {
            wmma::fragment<wmma::matrix_a, 16, 16, 8, wmma::precision::tf32, wmma::col_major> af[4];
            wmma::fragment<wmma::matrix_b, 16, 16, 8, wmma::precision::tf32, wmma::row_major> bf[4];
            #pragma unroll
            for (int i = 0; i < 4; i++) {
                wmma::load_matrix_sync(af[i], sA + kk * 132 + wm * 64 + i * 16, 132);
                #pragma unroll
                for (int t = 0; t < af[i].num_elements; t++)
                    af[i].x[t] = wmma::__float_to_tf32(af[i].x[t]);
            }
            #pragma unroll
            for (int j = 0; j < 4; j++) {
                wmma::load_matrix_sync(bf[j], sB + kk * 260 + wn * 64 + j * 16, 260);
                #pragma unroll
                for (int t = 0; t < bf[j].num_elements; t++)
                    bf[j].x[t] = wmma::__float_to_tf32(bf[j].x[t]);
            }
            #pragma unroll
            for (int i = 0; i < 4; i++)
                #pragma unroll
                for (int j = 0; j < 4; j++)
                    wmma::mma_sync(c[i][j], af[i], bf[j], c[i][j]);
        }
        __syncthreads();
    }

    // ---- reorganize: fragment tiles -> sI[r=(b_l*8+d_l)][k=(c*32+e)] ------
    float* sI = sm;            // 32 x 1032
    #pragma unroll
    for (int i = 0; i < 4; i++)
        #pragma unroll
        for (int j = 0; j < 4; j++) {
            int ml = wm * 64 + i * 16, nl = wn * 64 + j * 16;
            int r = (ml >> 5) * 8 + (nl >> 5);
            wmma::store_matrix_sync(sI + (size_t)r * 1032 + (ml & 31) * 32 + (nl & 31),
                                    c[i][j], 32, wmma::mem_row_major);
        }
    __syncthreads();

    // ---- fused W-contraction: [32 x 1024] @ [1024 x 128] ------------------
    wmma::fragment<wmma::accumulator, 16, 16, 8, float> o[2];
    wmma::fill_fragment(o[0], 0.0f);
    wmma::fill_fragment(o[1], 0.0f);

    load_stage_W(smb, tid, 0, 0, ow);
    cp_commit();
    for (int kc = 0; kc < 32; kc++) {
        int s = kc & 1;
        if (kc + 1 < 32) load_stage_W(smb, tid, kc + 1, s ^ 1, ow);
        cp_commit();
        cp_wait1();
        __syncthreads();
        float* sWc = sm + 33024 + s * 4224;
        #pragma unroll
        for (int kk = 0; kk < 32; kk += 8) {
            wmma::fragment<wmma::matrix_a, 16, 16, 8, wmma::precision::tf32, wmma::row_major> af;
            wmma::load_matrix_sync(af, sI + (wm * 16) * 1032 + kc * 32 + kk, 1032);
            #pragma unroll
            for (int t = 0; t < af.num_elements; t++)
                af.x[t] = wmma::__float_to_tf32(af.x[t]);
            #pragma unroll
            for (int j = 0; j < 2; j++) {
                wmma::fragment<wmma::matrix_b, 16, 16, 8, wmma::precision::tf32, wmma::row_major> bf;
                wmma::load_matrix_sync(bf, sWc + kk * 132 + wn * 32 + j * 16, 132);
                #pragma unroll
                for (int t = 0; t < bf.num_elements; t++)
                    bf.x[t] = wmma::__float_to_tf32(bf.x[t]);
                wmma::mma_sync(o[j], af, bf, o[j]);
            }
        }
        __syncthreads();
    }

    // ---- output epilogue: scale by rinv, add bias, store ------------------
    float* sO = sm + 33024;    // 32 x 132
    #pragma unroll
    for (int j = 0; j < 2; j++)
        wmma::store_matrix_sync(sO + (wm * 16) * 132 + wn * 32 + j * 16, o[j],
                                132, wmma::mem_row_major);
    __syncthreads();

    const int b0 = blockIdx.y * 4, d0 = blockIdx.x * 8;
    #pragma unroll
    for (int it = 0; it < 4; it++) {
        int flat = tid + it * 256;           // 1024 float4s = 32x128
        int r = flat >> 5, fc = (flat & 31) << 2;
        float4 v  = *(float4*)(sO + r * 132 + fc);
        int orow  = (b0 + (r >> 3)) * NR + d0 + (r & 7);
        float rv  = g_rinv[orow];
        float4 bb = *(const float4*)(ob + fc);
        float4 w  = { v.x * rv + bb.x, v.y * rv + bb.y,
                      v.z * rv + bb.z, v.w * rv + bb.w };
        *(float4*)(out + (size_t)orow * 128 + fc) = w;
    }
}

// ---------------------------------------------------------------------------
extern "C" void kernel_launch(void* const* d_in, const int* in_sizes, int n_in,
                              void* d_out, int out_size)
{
    const float* act      = (const float*)d_in[0];
    const float* mask     = (const float*)d_in[1];
    const float* ln_scale = (const float*)d_in[2];
    const float* ln_off   = (const float*)d_in[3];
    const float* left_w   = (const float*)d_in[4];
    const float* left_b   = (const float*)d_in[5];
    const float* right_w  = (const float*)d_in[6];
    const float* right_b  = (const float*)d_in[7];
    const float* out_w    = (const float*)d_in[8];
    const float* out_b    = (const float*)d_in[9];
    float* out = (float*)d_out;

    const int smem1 = (64 * 260 + 256 * 64 + 64) * 4;       // 132352
    const int smem3 = (33024 + 2 * 4224) * 4;               // 165888
    cudaFuncSetAttribute(ln_proj_kernel,    cudaFuncAttributeMaxDynamicSharedMemorySize, smem1);
    cudaFuncSetAttribute(gemm_fused_kernel, cudaFuncAttributeMaxDynamicSharedMemorySize, smem3);

    ln_proj_kernel<<<(NS * NR) / 64, 256, smem1>>>(act, mask, ln_scale, ln_off,
                                                   left_w, left_b, right_w, right_b);
    norm_kernel<<<NR, NR>>>(mask);
    gemm_fused_kernel<<<dim3(MT / 256, MT / 128), 256, smem3>>>(out_w, out_b, out);
}